// round 17
// baseline (speedup 1.0000x reference)
#include <cuda_runtime.h>
#include <cuda_bf16.h>
#include <cuda_fp8.h>
#include <mma.h>
#include <math.h>
#include <stdint.h>

using namespace nvcuda;
typedef __nv_bfloat16 bf16;

#define TOK     16384
#define DMODEL  1024
#define HID     4096
#define NSEQ    256
#define DKH     128
#define QKVN    3072

#define WSCALE   256.f     // weight fp8 scale
#define ATTSCALE 128.f     // attention-output fp8 scale
#define H1SCALE  128.f     // gelu-output fp8 scale

// ---------------- scratch ----------------
__device__ uint8_t g_xn    [2L*TOK*DMODEL];   // fp8 LN outputs (scale 1)
__device__ bf16    g_qkv   [2L*TOK*QKVN];     // bf16 (feeds attention)
__device__ uint8_t g_attn  [2L*TOK*DMODEL];   // fp8 x ATTSCALE
__device__ float   g_attres[2L*TOK*DMODEL];
__device__ uint8_t g_h1    [2L*TOK*HID];      // fp8 x H1SCALE
__device__ uint8_t g_wqkv  [2L*QKVN*DMODEL];  // fp8 x WSCALE, [N,K]
__device__ uint8_t g_wo    [2L*DMODEL*DMODEL];
__device__ uint8_t g_w1    [2L*HID*DMODEL];
__device__ uint8_t g_w2    [2L*DMODEL*HID];

// ---------------- helpers ----------------
__device__ __forceinline__ void cp_async16(void* d, const void* s) {
    unsigned ds = (unsigned)__cvta_generic_to_shared(d);
    asm volatile("cp.async.cg.shared.global [%0], [%1], 16;\n" :: "r"(ds), "l"(s));
}
__device__ __forceinline__ void cp_commit() { asm volatile("cp.async.commit_group;\n"); }

__device__ __forceinline__ uint32_t f2e4m3(float x) {
    return (uint32_t)__nv_cvt_float_to_fp8(x, __NV_SATFINITE, __NV_E4M3);
}
__device__ __forceinline__ uint32_t pack4_e4m3(float a, float b, float c, float d) {
    return f2e4m3(a) | (f2e4m3(b) << 8) | (f2e4m3(c) << 16) | (f2e4m3(d) << 24);
}

__device__ __forceinline__ void mma_fp8(float4& c, const uint32_t* a, const uint32_t* b) {
    asm volatile("mma.sync.aligned.m16n8k32.row.col.f32.e4m3.e4m3.f32 "
        "{%0,%1,%2,%3}, {%4,%5,%6,%7}, {%8,%9}, {%0,%1,%2,%3};"
        : "+f"(c.x), "+f"(c.y), "+f"(c.z), "+f"(c.w)
        : "r"(a[0]), "r"(a[1]), "r"(a[2]), "r"(a[3]), "r"(b[0]), "r"(b[1]));
}

// ---------------- transpose + fp32 -> fp8(xWSCALE): src[K,N] -> dst[N,K], z slices ----------------
__global__ void cvtT_kernel(const float* __restrict__ src, uint8_t* __restrict__ dst, int K, int N) {
    __shared__ float t[32][33];
    long zo = (long)blockIdx.z * (long)K * N;
    int n0 = blockIdx.x * 32, k0 = blockIdx.y * 32;
    int tx = threadIdx.x & 31, ty = threadIdx.x >> 5;
#pragma unroll
    for (int i = 0; i < 32; i += 8)
        t[ty + i][tx] = src[zo + (long)(k0 + ty + i) * N + n0 + tx];
    __syncthreads();
#pragma unroll
    for (int i = 0; i < 32; i += 8)
        dst[zo + (long)(n0 + ty + i) * K + k0 + tx] = (uint8_t)f2e4m3(t[tx][ty + i] * WSCALE);
}

// ---------------- LayerNorm (fp32 in -> fp8 out, scale 1) ----------------
__global__ void ln_kernel(const float* __restrict__ x, const float* __restrict__ gamma,
                          const float* __restrict__ beta, uint8_t* __restrict__ out) {
    int warp = threadIdx.x >> 5, lane = threadIdx.x & 31;
    long row = (long)blockIdx.x * 8 + warp;
    const float* xr = x + row * DMODEL;
    float4 v[8];
    float s = 0.f, s2 = 0.f;
#pragma unroll
    for (int i = 0; i < 8; i++) {
        v[i] = *reinterpret_cast<const float4*>(xr + i * 128 + lane * 4);
        s  += v[i].x + v[i].y + v[i].z + v[i].w;
        s2 += v[i].x*v[i].x + v[i].y*v[i].y + v[i].z*v[i].z + v[i].w*v[i].w;
    }
#pragma unroll
    for (int o = 16; o > 0; o >>= 1) {
        s  += __shfl_xor_sync(0xffffffffu, s,  o);
        s2 += __shfl_xor_sync(0xffffffffu, s2, o);
    }
    float m  = s * (1.f / 1024.f);
    float var = s2 * (1.f / 1024.f) - m * m;
    float rs = rsqrtf(var + 1e-5f);
    uint8_t* orow = out + row * DMODEL;
#pragma unroll
    for (int i = 0; i < 8; i++) {
        int c = i * 128 + lane * 4;
        float4 g4 = *reinterpret_cast<const float4*>(gamma + c);
        float4 b4 = *reinterpret_cast<const float4*>(beta + c);
        float o0 = (v[i].x - m) * rs * g4.x + b4.x;
        float o1 = (v[i].y - m) * rs * g4.y + b4.y;
        float o2 = (v[i].z - m) * rs * g4.z + b4.z;
        float o3 = (v[i].w - m) * rs * g4.w + b4.w;
        *reinterpret_cast<uint32_t*>(orow + c) = pack4_e4m3(o0, o1, o2, o3);
    }
}

// ---------------- FP8 GEMM: C[M,Nfull] = dsc * (A[M,K] @ Bt[N,K]^T) + epilogue ----------------
// CTA 128x128, 4 warps of 64x64, BK=64 bytes, 4-stage cp.async, one barrier/iter, occ 2.
// EPI 0: bf16 out = acc*dsc + bias
// EPI 1: fp8  out = H1SCALE * gelu(acc*dsc + bias)
// EPI 2: f32  out = c[ci_res]*res + c[ci_out]*(acc*dsc + bias)
#define PIPE   4
#define LDP    80
#define ATILE  (128 * LDP)            // 10240 B
#define STGB   (2 * ATILE)            // 20480 B
#define EOFF   (PIPE * STGB)          // 81920
#define EBW    68
#define GSMEM  (EOFF + 4 * EBW * 16 * 4)  // 81920 + 17408 = 99328

template <int EPI>
__global__ void __launch_bounds__(128, 2) fgemm_kernel(
    const uint8_t* __restrict__ A, const uint8_t* __restrict__ Bt,
    const float* __restrict__ bias, const float* __restrict__ res,
    const float* __restrict__ coeffs, int ci_res, int ci_out, float dsc,
    void* __restrict__ Cout, int Nfull, int K)
{
    extern __shared__ char sm[];
    int tid = threadIdx.x, wid = tid >> 5, lane = tid & 31;
    int gid = lane >> 2, tig = lane & 3;
    int warpM = wid & 1, warpN = wid >> 1;
    long bm = (long)blockIdx.y * 128;
    long bn = (long)blockIdx.x * 128;
    int KT = K >> 6;

    float4 acc[4][8];
#pragma unroll
    for (int i = 0; i < 4; i++)
#pragma unroll
        for (int j = 0; j < 8; j++) acc[i][j] = make_float4(0.f, 0.f, 0.f, 0.f);

    // prologue: stages 0..2  (per operand per stage: 128 rows x 64B = 512 x 16B chunks)
#pragma unroll
    for (int s = 0; s < PIPE - 1; s++) {
        char* stg = sm + s * STGB;
        long koff = (long)s * 64;
#pragma unroll
        for (int i = 0; i < 4; i++) {
            int id = tid + i * 128;
            int r = id >> 2, c16 = (id & 3) * 16;
            cp_async16(stg + r * LDP + c16, A + (bm + r) * K + koff + c16);
            cp_async16(stg + ATILE + r * LDP + c16, Bt + (bn + r) * K + koff + c16);
        }
        cp_commit();
    }

    for (int kt = 0; kt < KT; kt++) {
        asm volatile("cp.async.wait_group 2;\n");
        __syncthreads();

        int pf = kt + PIPE - 1;
        if (pf < KT) {
            char* stg = sm + (pf & 3) * STGB;
            long koff = (long)pf * 64;
#pragma unroll
            for (int i = 0; i < 4; i++) {
                int id = tid + i * 128;
                int r = id >> 2, c16 = (id & 3) * 16;
                cp_async16(stg + r * LDP + c16, A + (bm + r) * K + koff + c16);
                cp_async16(stg + ATILE + r * LDP + c16, Bt + (bn + r) * K + koff + c16);
            }
        }
        cp_commit();

        char* As = sm + (kt & 3) * STGB;
        char* Bs = As + ATILE;
#pragma unroll
        for (int ks = 0; ks < 2; ks++) {
            int kb = ks * 32;
            uint32_t a[4][4], b[8][2];
#pragma unroll
            for (int i = 0; i < 4; i++) {
                int r0 = (warpM * 64 + i * 16 + gid) * LDP;
                a[i][0] = *(const uint32_t*)(As + r0 + kb + 4 * tig);
                a[i][1] = *(const uint32_t*)(As + r0 + 8 * LDP + kb + 4 * tig);
                a[i][2] = *(const uint32_t*)(As + r0 + kb + 16 + 4 * tig);
                a[i][3] = *(const uint32_t*)(As + r0 + 8 * LDP + kb + 16 + 4 * tig);
            }
#pragma unroll
            for (int j = 0; j < 8; j++) {
                int rb = (warpN * 64 + j * 8 + gid) * LDP;
                b[j][0] = *(const uint32_t*)(Bs + rb + kb + 4 * tig);
                b[j][1] = *(const uint32_t*)(Bs + rb + kb + 16 + 4 * tig);
            }
#pragma unroll
            for (int i = 0; i < 4; i++)
#pragma unroll
                for (int j = 0; j < 8; j++)
                    mma_fp8(acc[i][j], a[i], b[j]);
        }
    }

    // ---- epilogue ----
    float* ebuf = (float*)(sm + EOFF + wid * (EBW * 16 * 4));
    float cr = 0.f, co = 0.f;
    if (EPI == 2) { cr = coeffs[ci_res]; co = coeffs[ci_out]; }
#pragma unroll
    for (int i = 0; i < 4; i++) {
#pragma unroll
        for (int j = 0; j < 8; j++) {
            *(float2*)&ebuf[gid * EBW + j * 8 + 2 * tig]       = make_float2(acc[i][j].x, acc[i][j].y);
            *(float2*)&ebuf[(gid + 8) * EBW + j * 8 + 2 * tig] = make_float2(acc[i][j].z, acc[i][j].w);
        }
        __syncwarp();
#pragma unroll
        for (int k = 0; k < 4; k++) {
            int idx = lane + k * 32;
            int row = idx >> 3, c8 = (idx & 7) * 8;
            float4 v0 = *(float4*)&ebuf[row * EBW + c8];
            float4 v1 = *(float4*)&ebuf[row * EBW + c8 + 4];
            long gr  = bm + warpM * 64 + i * 16 + row;
            long gc0 = bn + warpN * 64 + c8;
            float4 b0 = *(const float4*)&bias[gc0];
            float4 b1 = *(const float4*)&bias[gc0 + 4];
            float o0 = v0.x * dsc + b0.x, o1 = v0.y * dsc + b0.y;
            float o2 = v0.z * dsc + b0.z, o3 = v0.w * dsc + b0.w;
            float o4 = v1.x * dsc + b1.x, o5 = v1.y * dsc + b1.y;
            float o6 = v1.z * dsc + b1.z, o7 = v1.w * dsc + b1.w;
            if (EPI == 0) {
                __nv_bfloat162 p0 = __floats2bfloat162_rn(o0, o1);
                __nv_bfloat162 p1 = __floats2bfloat162_rn(o2, o3);
                __nv_bfloat162 p2 = __floats2bfloat162_rn(o4, o5);
                __nv_bfloat162 p3 = __floats2bfloat162_rn(o6, o7);
                *(uint4*)&((bf16*)Cout)[gr * Nfull + gc0] =
                    make_uint4(*(uint32_t*)&p0, *(uint32_t*)&p1, *(uint32_t*)&p2, *(uint32_t*)&p3);
            } else if (EPI == 1) {
                o0 = 0.5f*o0*(1.f+erff(o0*0.70710678f)); o1 = 0.5f*o1*(1.f+erff(o1*0.70710678f));
                o2 = 0.5f*o2*(1.f+erff(o2*0.70710678f)); o3 = 0.5f*o3*(1.f+erff(o3*0.70710678f));
                o4 = 0.5f*o4*(1.f+erff(o4*0.70710678f)); o5 = 0.5f*o5*(1.f+erff(o5*0.70710678f));
                o6 = 0.5f*o6*(1.f+erff(o6*0.70710678f)); o7 = 0.5f*o7*(1.f+erff(o7*0.70710678f));
                uint2 w;
                w.x = pack4_e4m3(o0 * H1SCALE, o1 * H1SCALE, o2 * H1SCALE, o3 * H1SCALE);
                w.y = pack4_e4m3(o4 * H1SCALE, o5 * H1SCALE, o6 * H1SCALE, o7 * H1SCALE);
                *(uint2*)&((uint8_t*)Cout)[gr * Nfull + gc0] = w;
            } else {
                float4 r0 = *(const float4*)&res[gr * Nfull + gc0];
                float4 r1 = *(const float4*)&res[gr * Nfull + gc0 + 4];
                *(float4*)&((float*)Cout)[gr * Nfull + gc0] =
                    make_float4(cr*r0.x + co*o0, cr*r0.y + co*o1, cr*r0.z + co*o2, cr*r0.w + co*o3);
                *(float4*)&((float*)Cout)[gr * Nfull + gc0 + 4] =
                    make_float4(cr*r1.x + co*o4, cr*r1.y + co*o5, cr*r1.z + co*o6, cr*r1.w + co*o7);
            }
        }
        __syncwarp();
    }
}

// ---------------- fused cross-attention (wmma bf16), fp8 output xATTSCALE ----------------
#define SMEM_ATT 197632

__global__ void __launch_bounds__(256) attn_kernel() {
    extern __shared__ char smraw[];
    bf16*  Ks = (bf16*)smraw;
    bf16*  Vs = Ks + 256 * 136;
    bf16*  Qs = Vs + 256 * 136;
    float* Ss = (float*)(Qs + 32 * 136);
    bf16*  Ps = (bf16*)(Ss + 32 * 256);
    float* Os = Ss;

    int tid = threadIdx.x, wid = tid >> 5, lane = tid & 31;
    int bx = blockIdx.x;
    int s  = bx >> 9;
    int bh = bx & 511;
    int b = bh >> 3, h = bh & 7;

    const bf16* qs_op = g_qkv + (long)(1 - s) * TOK * QKVN;
    const bf16* qs_s  = g_qkv + (long)s * TOK * QKVN;
    const bf16* Qg = qs_op + ((long)b * NSEQ) * QKVN + 0 * DMODEL + h * DKH;
    const bf16* Kg = qs_s  + ((long)b * NSEQ) * QKVN + 1 * DMODEL + h * DKH;
    const bf16* Vg = qs_s  + ((long)b * NSEQ) * QKVN + 2 * DMODEL + h * DKH;
    uint8_t*    Og = g_attn + (long)s * TOK * DMODEL + ((long)b * NSEQ) * DMODEL + h * DKH;

#pragma unroll
    for (int i = 0; i < 16; i++) {
        int v = tid + i * 256;
        int r = v >> 4, c8 = (v & 15) * 8;
        *(uint4*)&Ks[r * 136 + c8] = *(const uint4*)&Kg[(long)r * QKVN + c8];
        *(uint4*)&Vs[r * 136 + c8] = *(const uint4*)&Vg[(long)r * QKVN + c8];
    }
    __syncthreads();

    const float scale = 0.08838834764831845f;

    for (int qc = 0; qc < 8; qc++) {
#pragma unroll
        for (int i = 0; i < 2; i++) {
            int v = tid + i * 256;
            int r = v >> 4, c8 = (v & 15) * 8;
            *(uint4*)&Qs[r * 136 + c8] = *(const uint4*)&Qg[(long)(qc * 32 + r) * QKVN + c8];
        }
        __syncthreads();

        {
            wmma::fragment<wmma::accumulator, 16, 16, 16, float> c[2][2];
#pragma unroll
            for (int i = 0; i < 2; i++)
#pragma unroll
                for (int j = 0; j < 2; j++) wmma::fill_fragment(c[i][j], 0.f);
#pragma unroll
            for (int kt = 0; kt < 8; kt++) {
                wmma::fragment<wmma::matrix_a, 16, 16, 16, bf16, wmma::row_major> a[2];
                wmma::fragment<wmma::matrix_b, 16, 16, 16, bf16, wmma::col_major> bb[2];
#pragma unroll
                for (int i = 0; i < 2; i++)
                    wmma::load_matrix_sync(a[i], &Qs[(i * 16) * 136 + kt * 16], 136);
#pragma unroll
                for (int j = 0; j < 2; j++)
                    wmma::load_matrix_sync(bb[j], &Ks[(wid * 32 + j * 16) * 136 + kt * 16], 136);
#pragma unroll
                for (int i = 0; i < 2; i++)
#pragma unroll
                    for (int j = 0; j < 2; j++)
                        wmma::mma_sync(c[i][j], a[i], bb[j], c[i][j]);
            }
#pragma unroll
            for (int i = 0; i < 2; i++)
#pragma unroll
                for (int j = 0; j < 2; j++) {
#pragma unroll
                    for (int t = 0; t < c[i][j].num_elements; t++) c[i][j].x[t] *= scale;
                    wmma::store_matrix_sync(&Ss[(i * 16) * 256 + wid * 32 + j * 16],
                                            c[i][j], 256, wmma::mem_row_major);
                }
        }
        __syncthreads();

        {
#pragma unroll
            for (int rq = 0; rq < 4; rq++) {
                int row = wid * 4 + rq;
                float* srow = Ss + row * 256;
                float vals[8];
                float mx = -1e30f;
#pragma unroll
                for (int i = 0; i < 8; i++) { vals[i] = srow[lane + i * 32]; mx = fmaxf(mx, vals[i]); }
#pragma unroll
                for (int o = 16; o > 0; o >>= 1) mx = fmaxf(mx, __shfl_xor_sync(0xffffffffu, mx, o));
                float sum = 0.f;
#pragma unroll
                for (int i = 0; i < 8; i++) { vals[i] = __expf(vals[i] - mx); sum += vals[i]; }
#pragma unroll
                for (int o = 16; o > 0; o >>= 1) sum += __shfl_xor_sync(0xffffffffu, sum, o);
                float inv = 1.f / sum;
#pragma unroll
                for (int i = 0; i < 8; i++)
                    Ps[row * 264 + lane + i * 32] = __float2bfloat16(vals[i] * inv);
            }
        }
        __syncthreads();

        {
            wmma::fragment<wmma::accumulator, 16, 16, 16, float> c2[2];
#pragma unroll
            for (int i = 0; i < 2; i++) wmma::fill_fragment(c2[i], 0.f);
#pragma unroll
            for (int kt = 0; kt < 16; kt++) {
                wmma::fragment<wmma::matrix_a, 16, 16, 16, bf16, wmma::row_major> a[2];
                wmma::fragment<wmma::matrix_b, 16, 16, 16, bf16, wmma::row_major> bb;
#pragma unroll
                for (int i = 0; i < 2; i++)
                    wmma::load_matrix_sync(a[i], &Ps[(i * 16) * 264 + kt * 16], 264);
                wmma::load_matrix_sync(bb, &Vs[(kt * 16) * 136 + wid * 16], 136);
#pragma unroll
                for (int i = 0; i < 2; i++) wmma::mma_sync(c2[i], a[i], bb, c2[i]);
            }
#pragma unroll
            for (int i = 0; i < 2; i++)
                wmma::store_matrix_sync(&Os[(i * 16) * 128 + wid * 16], c2[i], 128, wmma::mem_row_major);
        }
        __syncthreads();

        // write fp8 x ATTSCALE (4 bytes per thread per iter)
#pragma unroll
        for (int i = 0; i < 4; i++) {
            int e = tid + i * 256;          // 1024 4-byte chunks = 32 rows x 128 cols
            int r = e >> 5, c4 = (e & 31) * 4;
            float* orow = Os + r * 128 + c4;
            *(uint32_t*)&Og[(long)(qc * 32 + r) * DMODEL + c4] =
                pack4_e4m3(orow[0] * ATTSCALE, orow[1] * ATTSCALE,
                           orow[2] * ATTSCALE, orow[3] * ATTSCALE);
        }
        __syncthreads();
    }
}

// ---------------- host ----------------
extern "C" void kernel_launch(void* const* d_in, const int* in_sizes, int n_in,
                              void* d_out, int out_size) {
    const float* rgb   = (const float*)d_in[0];
    const float* ir    = (const float*)d_in[1];
    const float* ln1g  = (const float*)d_in[2];
    const float* ln1b  = (const float*)d_in[3];
    const float* ln2g  = (const float*)d_in[4];
    const float* ln2b  = (const float*)d_in[5];
    const float* Wqv   = (const float*)d_in[6];
    const float* bqv   = (const float*)d_in[7];
    const float* Wqi   = (const float*)d_in[8];
    const float* bqi   = (const float*)d_in[9];
    const float* Wov   = (const float*)d_in[10];
    const float* bov   = (const float*)d_in[11];
    const float* Woi   = (const float*)d_in[12];
    const float* boi   = (const float*)d_in[13];
    const float* blkg  = (const float*)d_in[14];
    const float* blkb  = (const float*)d_in[15];
    const float* W1v   = (const float*)d_in[16];
    const float* b1v   = (const float*)d_in[17];
    const float* W2v   = (const float*)d_in[18];
    const float* b2v   = (const float*)d_in[19];
    const float* W1i   = (const float*)d_in[20];
    const float* b1i   = (const float*)d_in[21];
    const float* W2i   = (const float*)d_in[22];
    const float* b2i   = (const float*)d_in[23];
    const float* coeffs = (const float*)d_in[24];

    uint8_t *xn, *attn, *h1, *wqkv, *wo, *w1, *w2;
    bf16 *qkv;
    float* attres;
    cudaGetSymbolAddress((void**)&xn, g_xn);
    cudaGetSymbolAddress((void**)&qkv, g_qkv);
    cudaGetSymbolAddress((void**)&attn, g_attn);
    cudaGetSymbolAddress((void**)&attres, g_attres);
    cudaGetSymbolAddress((void**)&h1, g_h1);
    cudaGetSymbolAddress((void**)&wqkv, g_wqkv);
    cudaGetSymbolAddress((void**)&wo, g_wo);
    cudaGetSymbolAddress((void**)&w1, g_w1);
    cudaGetSymbolAddress((void**)&w2, g_w2);

    const long DD = (long)DMODEL * DMODEL;
    const long TD = (long)TOK * DMODEL;
    const long QD = (long)TOK * QKVN;

    const float DSC_QKV  = 1.f / WSCALE;
    const float DSC_PROJ = 1.f / (WSCALE * ATTSCALE);
    const float DSC_MLP1 = 1.f / WSCALE;
    const float DSC_MLP2 = 1.f / (WSCALE * H1SCALE);

    cudaFuncSetAttribute(fgemm_kernel<0>, cudaFuncAttributeMaxDynamicSharedMemorySize, GSMEM);
    cudaFuncSetAttribute(fgemm_kernel<1>, cudaFuncAttributeMaxDynamicSharedMemorySize, GSMEM);
    cudaFuncSetAttribute(fgemm_kernel<2>, cudaFuncAttributeMaxDynamicSharedMemorySize, GSMEM);
    cudaFuncSetAttribute(attn_kernel, cudaFuncAttributeMaxDynamicSharedMemorySize, SMEM_ATT);

    // interleaved so launch indices 2 AND 5 are both fgemm (for ncu capture)
    cvtT_kernel<<<dim3(DMODEL/32, DMODEL/32, 3), 256>>>(Wqv, wqkv, DMODEL, DMODEL);        // #0
    ln_kernel<<<TOK / 8, 256>>>(rgb, ln1g, ln1b, xn);                                      // #1
    fgemm_kernel<0><<<dim3(QKVN/128, TOK/128), 128, GSMEM>>>(                              // #2
        xn, wqkv, bqv, nullptr, nullptr, 0, 0, DSC_QKV, qkv, QKVN, DMODEL);
    cvtT_kernel<<<dim3(DMODEL/32, DMODEL/32, 3), 256>>>(Wqi, wqkv + 3 * DD, DMODEL, DMODEL); // #3
    ln_kernel<<<TOK / 8, 256>>>(ir, ln2g, ln2b, xn + TD);                                  // #4
    fgemm_kernel<0><<<dim3(QKVN/128, TOK/128), 128, GSMEM>>>(                              // #5
        xn + TD, wqkv + 3 * DD, bqi, nullptr, nullptr, 0, 0, DSC_QKV, qkv + QD, QKVN, DMODEL);

    // remaining weight converts
    cvtT_kernel<<<dim3(DMODEL/32, DMODEL/32, 1), 256>>>(Wov, wo, DMODEL, DMODEL);
    cvtT_kernel<<<dim3(DMODEL/32, DMODEL/32, 1), 256>>>(Woi, wo + DD, DMODEL, DMODEL);
    cvtT_kernel<<<dim3(HID/32, DMODEL/32, 1), 256>>>(W1v, w1, DMODEL, HID);
    cvtT_kernel<<<dim3(HID/32, DMODEL/32, 1), 256>>>(W1i, w1 + (long)HID * DMODEL, DMODEL, HID);
    cvtT_kernel<<<dim3(DMODEL/32, HID/32, 1), 256>>>(W2v, w2, HID, DMODEL);
    cvtT_kernel<<<dim3(DMODEL/32, HID/32, 1), 256>>>(W2i, w2 + (long)DMODEL * HID, HID, DMODEL);

    // fused cross attention (bf16 in, fp8 out)
    attn_kernel<<<1024, 256, SMEM_ATT>>>();

    // output projection + coeff residual -> fp32 attres
    for (int s = 0; s < 2; s++) {
        fgemm_kernel<2><<<dim3(DMODEL/128, TOK/128), 128, GSMEM>>>(
            attn + s * TD, wo + s * DD, s ? boi : bov,
            s ? ir : rgb, coeffs, 2 * s, 2 * s + 1, DSC_PROJ,
            attres + s * TD, DMODEL, DMODEL);
    }

    // block LN (shared params) -> fp8
    ln_kernel<<<TOK / 8, 256>>>(attres, blkg, blkb, xn);
    ln_kernel<<<TOK / 8, 256>>>(attres + TD, blkg, blkb, xn + TD);

    // MLP1 (gelu, fp8 out x H1SCALE)
    for (int s = 0; s < 2; s++) {
        fgemm_kernel<1><<<dim3(HID/128, TOK/128), 128, GSMEM>>>(
            xn + s * TD, w1 + (long)s * HID * DMODEL, s ? b1i : b1v,
            nullptr, nullptr, 0, 0, DSC_MLP1,
            h1 + (long)s * TOK * HID, HID, DMODEL);
    }

    // MLP2 + coeff residual -> d_out (fp32)
    for (int s = 0; s < 2; s++) {
        fgemm_kernel<2><<<dim3(DMODEL/128, TOK/128), 128, GSMEM>>>(
            h1 + (long)s * TOK * HID, w2 + (long)s * DMODEL * HID, s ? b2i : b2v,
            attres + s * TD, coeffs, 4 + 2 * s, 5 + 2 * s, DSC_MLP2,
            (float*)d_out + s * TD, DMODEL, HID);
    }
}